// round 1
// baseline (speedup 1.0000x reference)
#include <cuda_runtime.h>
#include <math.h>

#define JN 25
#define CIN 3
#define HID 64
#define LAT 32

#define SPB 10          // samples per block
#define NT  256         // threads per block (250 active compute lanes)
#define PROW 36         // padded P row stride (floats)
#define PSAMP (JN*PROW + 4)   // 904 floats per sample, bank-staggered
#define QSAMP 100       // Q per-sample stride: 25 rows * 4 (padded)

// shared layout offsets (in floats)
#define OFF_W1   0        // 192
#define OFF_B1   192      // 64
#define OFF_W2   256      // 2048
#define OFF_W3   2304     // 2048
#define OFF_B23  4352     // 64
#define OFF_W4   4416     // 256 (64x4 padded)
#define OFF_B4   4672     // 4
#define OFF_A1   4676     // 628
#define OFF_A23  5304     // 628
#define OFF_A4   5932     // 628
#define OFF_IO   6560     // 752 (10*75 rounded)
#define OFF_P    7312     // 9040 (10*904)
#define OFF_Q    16352    // 1000 (10*100)
#define SMEM_FLOATS 17352
#define SMEM_BYTES (SMEM_FLOATS * 4)

typedef unsigned long long u64;

__device__ float g_A1s[JN*JN];
__device__ float g_A2s[JN*JN];
__device__ float g_A3s[JN*JN];
__device__ float g_A23[JN*JN];
__device__ float g_A4s[JN*JN];
__device__ float g_b23[HID];

// ---------- f32x2 helpers (sm_100+ packed fp32) ----------
__device__ __forceinline__ u64 pk2(float v) {
    u64 r; asm("mov.b64 %0, {%1, %1};" : "=l"(r) : "f"(v)); return r;
}
__device__ __forceinline__ void upk(u64 v, float& lo, float& hi) {
    asm("mov.b64 {%0, %1}, %2;" : "=f"(lo), "=f"(hi) : "l"(v));
}
__device__ __forceinline__ u64 ffma2(u64 a, u64 b, u64 c) {
    u64 d; asm("fma.rn.f32x2 %0, %1, %2, %3;" : "=l"(d) : "l"(a), "l"(b), "l"(c)); return d;
}

// ---------- prep: softmax(A), A23 = A3s@A2s, b23 = b2@W3 + b3 ----------
__global__ void prep_kernel(const float* __restrict__ A1, const float* __restrict__ A2,
                            const float* __restrict__ A3, const float* __restrict__ A4,
                            const float* __restrict__ b2, const float* __restrict__ W3,
                            const float* __restrict__ b3)
{
    int t = threadIdx.x;
    if (t < 4*JN) {
        int m = t / JN;
        int r = t % JN;
        const float* src = (m==0) ? A1 : (m==1) ? A2 : (m==2) ? A3 : A4;
        float*       dst = (m==0) ? g_A1s : (m==1) ? g_A2s : (m==2) ? g_A3s : g_A4s;
        float mx = -1e30f;
        for (int k = 0; k < JN; k++) mx = fmaxf(mx, src[r*JN+k]);
        float e[JN]; float s = 0.f;
        for (int k = 0; k < JN; k++) { e[k] = expf(src[r*JN+k] - mx); s += e[k]; }
        float inv = 1.f / s;
        for (int k = 0; k < JN; k++) dst[r*JN+k] = e[k] * inv;
    }
    if (t >= 128 && t < 128 + HID) {
        int d = t - 128;
        float acc = b3[d];
        for (int c = 0; c < LAT; c++) acc = fmaf(b2[c], W3[c*HID+d], acc);
        g_b23[d] = acc;
    }
    __syncthreads();
    for (int i = t; i < JN*JN; i += blockDim.x) {
        int r = i / JN, c = i % JN;
        float acc = 0.f;
        for (int k = 0; k < JN; k++) acc = fmaf(g_A3s[r*JN+k], g_A2s[k*JN+c], acc);
        g_A23[i] = acc;
    }
}

// ---------- main fused kernel ----------
__global__ void __launch_bounds__(NT, 2) gcn_kernel(
    const float* __restrict__ x,
    const float* __restrict__ W1, const float* __restrict__ b1,
    const float* __restrict__ W2,
    const float* __restrict__ W3,
    const float* __restrict__ W4, const float* __restrict__ b4,
    float* __restrict__ out, int S_total)
{
    extern __shared__ float sm[];
    float* sW1  = sm + OFF_W1;
    float* sb1  = sm + OFF_B1;
    float* sW2  = sm + OFF_W2;
    float* sW3  = sm + OFF_W3;
    float* sb23 = sm + OFF_B23;
    float* sW4  = sm + OFF_W4;
    float* sb4  = sm + OFF_B4;
    float* sA1  = sm + OFF_A1;
    float* sA23 = sm + OFF_A23;
    float* sA4  = sm + OFF_A4;
    float* sIO  = sm + OFF_IO;
    float* sP   = sm + OFF_P;
    float* sQ   = sm + OFF_Q;

    const int t = threadIdx.x;

    // ---- stage shared constants ----
    for (int i = t; i < CIN*HID; i += NT) sW1[i] = W1[i];
    for (int i = t; i < HID; i += NT) { sb1[i] = b1[i]; sb23[i] = g_b23[i]; }
    for (int i = t; i < HID*LAT; i += NT) sW2[i] = W2[i];
    for (int i = t; i < LAT*HID; i += NT) sW3[i] = W3[i];
    for (int i = t; i < HID*4; i += NT) {
        int c = i >> 2, d = i & 3;
        sW4[i] = (d < 3) ? W4[c*3 + d] : 0.f;
    }
    if (t < 4) sb4[t] = (t < 3) ? b4[t] : 0.f;
    for (int i = t; i < JN*JN; i += NT) { sA1[i] = g_A1s[i]; sA23[i] = g_A23[i]; sA4[i] = g_A4s[i]; }

    // ---- stage input samples ----
    const int s0 = blockIdx.x * SPB;
    const int nS = min(SPB, S_total - s0);
    const int nF = nS * JN * CIN;
    const float* xg = x + (size_t)s0 * (JN*CIN);
    for (int i = t; i < nF; i += NT) sIO[i] = xg[i];
    __syncthreads();

    const int s = t / JN;
    const int j = t % JN;
    const bool active = (t < SPB*JN) && (s < nS);

    if (active) {
        // stage 1: X' = A1s @ X  (mix on 3 input channels)
        float xp0 = 0.f, xp1 = 0.f, xp2 = 0.f;
        {
            const float* arow = sA1 + j*JN;
            const float* xs = sIO + s*(JN*CIN);
            #pragma unroll
            for (int k = 0; k < JN; k++) {
                float a = arow[k];
                xp0 = fmaf(a, xs[k*3+0], xp0);
                xp1 = fmaf(a, xs[k*3+1], xp1);
                xp2 = fmaf(a, xs[k*3+2], xp2);
            }
        }
        // stage 2: H = relu(X' @ W1 + b1)    [64]
        float H[HID];
        {
            u64 acc[HID/2];
            const u64* b1p = (const u64*)sb1;
            #pragma unroll
            for (int p = 0; p < HID/2; p++) acc[p] = b1p[p];
            u64 a0 = pk2(xp0), a1 = pk2(xp1), a2 = pk2(xp2);
            const ulonglong2* w0 = (const ulonglong2*)(sW1 + 0*HID);
            const ulonglong2* w1 = (const ulonglong2*)(sW1 + 1*HID);
            const ulonglong2* w2 = (const ulonglong2*)(sW1 + 2*HID);
            #pragma unroll
            for (int p = 0; p < HID/4; p++) {
                ulonglong2 v0 = w0[p], v1 = w1[p], v2 = w2[p];
                acc[2*p]   = ffma2(a0, v0.x, acc[2*p]);
                acc[2*p+1] = ffma2(a0, v0.y, acc[2*p+1]);
                acc[2*p]   = ffma2(a1, v1.x, acc[2*p]);
                acc[2*p+1] = ffma2(a1, v1.y, acc[2*p+1]);
                acc[2*p]   = ffma2(a2, v2.x, acc[2*p]);
                acc[2*p+1] = ffma2(a2, v2.y, acc[2*p+1]);
            }
            #pragma unroll
            for (int p = 0; p < HID/2; p++) {
                float lo, hi; upk(acc[p], lo, hi);
                H[2*p]   = fmaxf(lo, 0.f);
                H[2*p+1] = fmaxf(hi, 0.f);
            }
        }
        // stage 3: P = H @ W2   [32]  (bias b2 folded into b23 downstream)
        {
            u64 pacc[LAT/2];
            #pragma unroll
            for (int p = 0; p < LAT/2; p++) pacc[p] = 0ull;
            #pragma unroll
            for (int k = 0; k < HID; k++) {
                u64 hk = pk2(H[k]);
                const ulonglong2* wr = (const ulonglong2*)(sW2 + k*LAT);
                #pragma unroll
                for (int p = 0; p < LAT/4; p++) {
                    ulonglong2 w = wr[p];
                    pacc[2*p]   = ffma2(hk, w.x, pacc[2*p]);
                    pacc[2*p+1] = ffma2(hk, w.y, pacc[2*p+1]);
                }
            }
            u64* prow = (u64*)(sP + s*PSAMP + j*PROW);
            #pragma unroll
            for (int p = 0; p < LAT/2; p++) prow[p] = pacc[p];
        }
    }
    __syncthreads();

    if (active) {
        // stage 4: M = A23 @ P   (mix on 32 latent channels; A23 = A3s@A2s)
        float M[LAT];
        {
            u64 macc[LAT/2];
            #pragma unroll
            for (int p = 0; p < LAT/2; p++) macc[p] = 0ull;
            const float* arow = sA23 + j*JN;
            const float* psamp = sP + s*PSAMP;
            #pragma unroll
            for (int k = 0; k < JN; k++) {
                u64 a = pk2(arow[k]);
                const ulonglong2* pr = (const ulonglong2*)(psamp + k*PROW);
                #pragma unroll
                for (int p = 0; p < LAT/4; p++) {
                    ulonglong2 v = pr[p];
                    macc[2*p]   = ffma2(a, v.x, macc[2*p]);
                    macc[2*p+1] = ffma2(a, v.y, macc[2*p+1]);
                }
            }
            #pragma unroll
            for (int p = 0; p < LAT/2; p++) upk(macc[p], M[2*p], M[2*p+1]);
        }
        // stage 5+6: Hd = relu(M @ W3 + b23); Q = Hd @ W4   [3]
        float q0 = 0.f, q1 = 0.f, q2 = 0.f;
        {
            u64 hacc[HID/2];
            const u64* b23p = (const u64*)sb23;
            #pragma unroll
            for (int p = 0; p < HID/2; p++) hacc[p] = b23p[p];
            #pragma unroll
            for (int k = 0; k < LAT; k++) {
                u64 mk = pk2(M[k]);
                const ulonglong2* wr = (const ulonglong2*)(sW3 + k*HID);
                #pragma unroll
                for (int p = 0; p < HID/4; p++) {
                    ulonglong2 w = wr[p];
                    hacc[2*p]   = ffma2(mk, w.x, hacc[2*p]);
                    hacc[2*p+1] = ffma2(mk, w.y, hacc[2*p+1]);
                }
            }
            #pragma unroll
            for (int p = 0; p < HID/2; p++) {
                float lo, hi; upk(hacc[p], lo, hi);
                lo = fmaxf(lo, 0.f); hi = fmaxf(hi, 0.f);
                float4 wlo = ((const float4*)sW4)[2*p];
                float4 whi = ((const float4*)sW4)[2*p+1];
                q0 = fmaf(lo, wlo.x, q0); q1 = fmaf(lo, wlo.y, q1); q2 = fmaf(lo, wlo.z, q2);
                q0 = fmaf(hi, whi.x, q0); q1 = fmaf(hi, whi.y, q1); q2 = fmaf(hi, whi.z, q2);
            }
        }
        float* qrow = sQ + s*QSAMP + j*4;
        qrow[0] = q0; qrow[1] = q1; qrow[2] = q2;
    }
    __syncthreads();

    if (active) {
        // stage 7: out = A4s @ Q + b4
        float o0 = sb4[0], o1 = sb4[1], o2 = sb4[2];
        const float* arow = sA4 + j*JN;
        const float* qs = sQ + s*QSAMP;
        #pragma unroll
        for (int k = 0; k < JN; k++) {
            float a = arow[k];
            o0 = fmaf(a, qs[k*4+0], o0);
            o1 = fmaf(a, qs[k*4+1], o1);
            o2 = fmaf(a, qs[k*4+2], o2);
        }
        float* orow = sIO + (s*JN + j)*CIN;   // sIO reuse: safe, reads done pre-sync
        orow[0] = o0; orow[1] = o1; orow[2] = o2;
    }
    __syncthreads();

    float* og = out + (size_t)s0 * (JN*CIN);
    for (int i = t; i < nF; i += NT) og[i] = sIO[i];
}

extern "C" void kernel_launch(void* const* d_in, const int* in_sizes, int n_in,
                              void* d_out, int out_size)
{
    const float* x  = (const float*)d_in[0];
    const float* A1 = (const float*)d_in[1];
    const float* W1 = (const float*)d_in[2];
    const float* b1 = (const float*)d_in[3];
    const float* A2 = (const float*)d_in[4];
    const float* W2 = (const float*)d_in[5];
    const float* b2 = (const float*)d_in[6];
    const float* A3 = (const float*)d_in[7];
    const float* W3 = (const float*)d_in[8];
    const float* b3 = (const float*)d_in[9];
    const float* A4 = (const float*)d_in[10];
    const float* W4 = (const float*)d_in[11];
    const float* b4 = (const float*)d_in[12];
    float* out = (float*)d_out;

    const int S_total = in_sizes[0] / (JN * CIN);   // 65536

    cudaFuncSetAttribute(gcn_kernel, cudaFuncAttributeMaxDynamicSharedMemorySize, SMEM_BYTES);

    prep_kernel<<<1, 256>>>(A1, A2, A3, A4, b2, W3, b3);

    const int grid = (S_total + SPB - 1) / SPB;
    gcn_kernel<<<grid, NT, SMEM_BYTES>>>(x, W1, b1, W2, W3, W4, b4, out, S_total);
}

// round 2
// speedup vs baseline: 2.1689x; 2.1689x over previous
#include <cuda_runtime.h>
#include <math.h>

#define JN 25
#define CIN 3
#define HID 64
#define LAT 32

#define NT   256
#define TPS  13            // threads per sample (2 joints each, 26th is dummy)
#define SPT  19            // samples per block
#define ACT  (TPS*SPT)     // 247 active threads

#define XROW   4           // padded x row (floats)
#define XSAMP  104         // 26*4
#define PROW   36          // P row stride (floats), 16B-aligned
#define PSAMP  936         // 26*36
#define QSAMP  108         // 26*4 + pad
#define OSAMP  78          // 26*3 packed out staging

// shared layout (floats)
#define OFF_W1B  0         // 256   [64][4] = (W1[0][k],W1[1][k],W1[2][k],b1[k])
#define OFF_W2   256       // 2048  [64][32]
#define OFF_W3T  2304      // 2048  [64][32] transposed
#define OFF_W4B  4352      // 256   [64][4] = (W4[d][0..2], b23[d])
#define OFF_A1   4608      // 652 (rows 0..24 real, row 25 zero)
#define OFF_A23  5260      // 652
#define OFF_A4   5912      // 652
#define OFF_B4   6564      // 4
#define OFF_X    6568      // 19*104 = 1976   (reused as out staging, 19*78=1482)
#define OFF_P    8544      // 19*936 = 17784
#define OFF_Q    26328     // 19*108 = 2052
#define SMEM_FLOATS 28380
#define SMEM_BYTES  (SMEM_FLOATS * 4)

typedef unsigned long long u64;

__device__ float g_A1s[JN*JN];
__device__ float g_A2s[JN*JN];
__device__ float g_A3s[JN*JN];
__device__ float g_A23[JN*JN];
__device__ float g_A4s[JN*JN];
__device__ float g_b23[HID];
__device__ float g_W1b[HID*4];
__device__ float g_W3t[HID*LAT];
__device__ float g_W4b[HID*4];

// ---------- f32x2 helpers ----------
__device__ __forceinline__ u64 pk2(float v) {
    u64 r; asm("mov.b64 %0, {%1, %1};" : "=l"(r) : "f"(v)); return r;
}
__device__ __forceinline__ void upk(u64 v, float& lo, float& hi) {
    asm("mov.b64 {%0, %1}, %2;" : "=f"(lo), "=f"(hi) : "l"(v));
}
__device__ __forceinline__ u64 ffma2(u64 a, u64 b, u64 c) {
    u64 d; asm("fma.rn.f32x2 %0, %1, %2, %3;" : "=l"(d) : "l"(a), "l"(b), "l"(c)); return d;
}
__device__ __forceinline__ u64 addf2(u64 a, u64 b) {
    u64 d; asm("add.rn.f32x2 %0, %1, %2;" : "=l"(d) : "l"(a), "l"(b)); return d;
}

// ---------- prep ----------
__global__ void prep_kernel(const float* __restrict__ A1, const float* __restrict__ A2,
                            const float* __restrict__ A3, const float* __restrict__ A4,
                            const float* __restrict__ W1, const float* __restrict__ b1,
                            const float* __restrict__ b2, const float* __restrict__ W3,
                            const float* __restrict__ b3, const float* __restrict__ W4)
{
    int t = threadIdx.x;
    if (t < 4*JN) {
        int m = t / JN, r = t % JN;
        const float* src = (m==0) ? A1 : (m==1) ? A2 : (m==2) ? A3 : A4;
        float*       dst = (m==0) ? g_A1s : (m==1) ? g_A2s : (m==2) ? g_A3s : g_A4s;
        float mx = -1e30f;
        for (int k = 0; k < JN; k++) mx = fmaxf(mx, src[r*JN+k]);
        float e[JN]; float s = 0.f;
        for (int k = 0; k < JN; k++) { e[k] = expf(src[r*JN+k] - mx); s += e[k]; }
        float inv = 1.f / s;
        for (int k = 0; k < JN; k++) dst[r*JN+k] = e[k] * inv;
    }
    if (t >= 128 && t < 128 + HID) {
        int d = t - 128;
        float acc = b3[d];
        for (int c = 0; c < LAT; c++) acc = fmaf(b2[c], W3[c*HID+d], acc);
        g_b23[d] = acc;
    }
    __syncthreads();
    for (int i = t; i < JN*JN; i += blockDim.x) {
        int r = i / JN, c = i % JN;
        float acc = 0.f;
        for (int k = 0; k < JN; k++) acc = fmaf(g_A3s[r*JN+k], g_A2s[k*JN+c], acc);
        g_A23[i] = acc;
    }
    for (int i = t; i < HID*LAT; i += blockDim.x) {
        int d = i / LAT, c = i % LAT;
        g_W3t[i] = W3[c*HID + d];
    }
    for (int i = t; i < HID; i += blockDim.x) {
        g_W1b[4*i+0] = W1[0*HID+i];
        g_W1b[4*i+1] = W1[1*HID+i];
        g_W1b[4*i+2] = W1[2*HID+i];
        g_W1b[4*i+3] = b1[i];
        g_W4b[4*i+0] = W4[i*3+0];
        g_W4b[4*i+1] = W4[i*3+1];
        g_W4b[4*i+2] = W4[i*3+2];
        g_W4b[4*i+3] = g_b23[i];
    }
}

// ---------- main fused kernel ----------
__global__ void __launch_bounds__(NT, 2) gcn_kernel(
    const float* __restrict__ x,
    const float* __restrict__ W2,
    const float* __restrict__ b4,
    float* __restrict__ out, int S_total)
{
    extern __shared__ float sm[];
    float* sW1b = sm + OFF_W1B;
    float* sW2  = sm + OFF_W2;
    float* sW3t = sm + OFF_W3T;
    float* sW4b = sm + OFF_W4B;
    float* sA1  = sm + OFF_A1;
    float* sA23 = sm + OFF_A23;
    float* sA4  = sm + OFF_A4;
    float* sB4  = sm + OFF_B4;
    float* sX   = sm + OFF_X;
    float* sP   = sm + OFF_P;
    float* sQ   = sm + OFF_Q;
    float* sOut = sm + OFF_X;   // reuse

    const int t = threadIdx.x;

    // ---- stage constants (vectorized where possible) ----
    for (int i = t; i < HID; i += NT) {
        ((float4*)sW1b)[i] = ((const float4*)g_W1b)[i];
        ((float4*)sW4b)[i] = ((const float4*)g_W4b)[i];
    }
    for (int i = t; i < HID*LAT/4; i += NT) {
        ((float4*)sW2)[i]  = ((const float4*)W2)[i];
        ((float4*)sW3t)[i] = ((const float4*)g_W3t)[i];
    }
    for (int i = t; i < 652; i += NT) {
        sA1[i]  = (i < JN*JN) ? g_A1s[i] : 0.f;
        sA23[i] = (i < JN*JN) ? g_A23[i] : 0.f;
        sA4[i]  = (i < JN*JN) ? g_A4s[i] : 0.f;
    }
    if (t < 4) sB4[t] = (t < 3) ? b4[t] : 0.f;

    // ---- stage input (padded rows of 4) ----
    const int s0 = blockIdx.x * SPT;
    const int nS = min(SPT, S_total - s0);
    const int nF = nS * JN * CIN;
    const float* xg = x + (size_t)s0 * (JN*CIN);
    for (int i = t; i < nF; i += NT) {
        int si = i / 75, r = i % 75;
        sX[si*XSAMP + (r/3)*4 + (r%3)] = xg[i];
    }
    __syncthreads();

    const int s  = t / TPS;
    const int tj = t % TPS;
    const int j0 = 2*tj;
    const int j1 = 2*tj + 1;        // may be dummy row 25 (zero A rows)
    const bool active = (t < ACT) && (s < nS);

    u64 macc0[16], macc1[16];

    if (active) {
        // ---- stage 1: X' = A1s @ X (2 rows) ----
        float xa0 = 0.f, xa1 = 0.f, xa2 = 0.f;
        float xb0 = 0.f, xb1 = 0.f, xb2 = 0.f;
        {
            const float* a0r = sA1 + j0*JN;
            const float* a1r = sA1 + j1*JN;
            const float4* xs = (const float4*)(sX + s*XSAMP);
            #pragma unroll
            for (int k = 0; k < JN; k++) {
                float4 xr = xs[k];
                float a0 = a0r[k], a1 = a1r[k];
                xa0 = fmaf(a0, xr.x, xa0); xa1 = fmaf(a0, xr.y, xa1); xa2 = fmaf(a0, xr.z, xa2);
                xb0 = fmaf(a1, xr.x, xb0); xb1 = fmaf(a1, xr.y, xb1); xb2 = fmaf(a1, xr.z, xb2);
            }
        }
        // ---- stage 2+3 fused: P = relu(X'@W1+b1) @ W2 (on the fly, no H array) ----
        u64 pacc0[16], pacc1[16];
        #pragma unroll
        for (int p = 0; p < 16; p++) { pacc0[p] = 0ull; pacc1[p] = 0ull; }
        #pragma unroll 4
        for (int k = 0; k < HID; k++) {
            float4 wb = ((const float4*)sW1b)[k];
            float h0 = fmaf(xa2, wb.z, fmaf(xa1, wb.y, fmaf(xa0, wb.x, wb.w)));
            float h1 = fmaf(xb2, wb.z, fmaf(xb1, wb.y, fmaf(xb0, wb.x, wb.w)));
            h0 = fmaxf(h0, 0.f); h1 = fmaxf(h1, 0.f);
            u64 h0p = pk2(h0), h1p = pk2(h1);
            const ulonglong2* wr = (const ulonglong2*)(sW2 + k*LAT);
            #pragma unroll
            for (int q = 0; q < 8; q++) {
                ulonglong2 w = wr[q];
                pacc0[2*q]   = ffma2(h0p, w.x, pacc0[2*q]);
                pacc0[2*q+1] = ffma2(h0p, w.y, pacc0[2*q+1]);
                pacc1[2*q]   = ffma2(h1p, w.x, pacc1[2*q]);
                pacc1[2*q+1] = ffma2(h1p, w.y, pacc1[2*q+1]);
            }
        }
        // store P rows (dummy row 25 lands in padding, never read)
        {
            ulonglong2* pr0 = (ulonglong2*)(sP + s*PSAMP + j0*PROW);
            ulonglong2* pr1 = (ulonglong2*)(sP + s*PSAMP + j1*PROW);
            #pragma unroll
            for (int q = 0; q < 8; q++) {
                ulonglong2 v0, v1;
                v0.x = pacc0[2*q]; v0.y = pacc0[2*q+1];
                v1.x = pacc1[2*q]; v1.y = pacc1[2*q+1];
                pr0[q] = v0; pr1[q] = v1;
            }
        }
    }
    __syncthreads();

    if (active) {
        // ---- stage 4: M = A23 @ P (2 rows) ----
        #pragma unroll
        for (int p = 0; p < 16; p++) { macc0[p] = 0ull; macc1[p] = 0ull; }
        {
            const float* a0r = sA23 + j0*JN;
            const float* a1r = sA23 + j1*JN;
            const float* ps  = sP + s*PSAMP;
            #pragma unroll 5
            for (int k = 0; k < JN; k++) {
                u64 a0 = pk2(a0r[k]);
                u64 a1 = pk2(a1r[k]);
                const ulonglong2* pr = (const ulonglong2*)(ps + k*PROW);
                #pragma unroll
                for (int q = 0; q < 8; q++) {
                    ulonglong2 w = pr[q];
                    macc0[2*q]   = ffma2(a0, w.x, macc0[2*q]);
                    macc0[2*q+1] = ffma2(a0, w.y, macc0[2*q+1]);
                    macc1[2*q]   = ffma2(a1, w.x, macc1[2*q]);
                    macc1[2*q+1] = ffma2(a1, w.y, macc1[2*q+1]);
                }
            }
        }
        // ---- stage 5+6 fused: Q = relu(M@W3 + b23) @ W4 (dot-product form) ----
        float q00 = 0.f, q01 = 0.f, q02 = 0.f;
        float q10 = 0.f, q11 = 0.f, q12 = 0.f;
        #pragma unroll 2
        for (int d = 0; d < HID; d++) {
            const ulonglong2* wr = (const ulonglong2*)(sW3t + d*LAT);
            u64 aA0 = 0ull, aB0 = 0ull, aA1 = 0ull, aB1 = 0ull;
            #pragma unroll
            for (int q = 0; q < 8; q++) {
                ulonglong2 w = wr[q];
                aA0 = ffma2(macc0[2*q],   w.x, aA0);
                aB0 = ffma2(macc0[2*q+1], w.y, aB0);
                aA1 = ffma2(macc1[2*q],   w.x, aA1);
                aB1 = ffma2(macc1[2*q+1], w.y, aB1);
            }
            float4 w4 = ((const float4*)sW4b)[d];
            float l0, h0, l1, h1;
            upk(addf2(aA0, aB0), l0, h0);
            upk(addf2(aA1, aB1), l1, h1);
            float hd0 = fmaxf(l0 + h0 + w4.w, 0.f);
            float hd1 = fmaxf(l1 + h1 + w4.w, 0.f);
            q00 = fmaf(hd0, w4.x, q00); q01 = fmaf(hd0, w4.y, q01); q02 = fmaf(hd0, w4.z, q02);
            q10 = fmaf(hd1, w4.x, q10); q11 = fmaf(hd1, w4.y, q11); q12 = fmaf(hd1, w4.z, q12);
        }
        float* qr0 = sQ + s*QSAMP + j0*4;
        float* qr1 = sQ + s*QSAMP + j1*4;
        qr0[0] = q00; qr0[1] = q01; qr0[2] = q02;
        qr1[0] = q10; qr1[1] = q11; qr1[2] = q12;
    }
    __syncthreads();

    if (active) {
        // ---- stage 7: out = A4s @ Q + b4 (2 rows) ----
        float o00 = sB4[0], o01 = sB4[1], o02 = sB4[2];
        float o10 = o00, o11 = o01, o12 = o02;
        const float* a0r = sA4 + j0*JN;
        const float* a1r = sA4 + j1*JN;
        const float4* qs = (const float4*)(sQ + s*QSAMP);
        #pragma unroll
        for (int k = 0; k < JN; k++) {
            float4 qr = qs[k];
            float a0 = a0r[k], a1 = a1r[k];
            o00 = fmaf(a0, qr.x, o00); o01 = fmaf(a0, qr.y, o01); o02 = fmaf(a0, qr.z, o02);
            o10 = fmaf(a1, qr.x, o10); o11 = fmaf(a1, qr.y, o11); o12 = fmaf(a1, qr.z, o12);
        }
        float* or0 = sOut + s*OSAMP + j0*3;
        float* or1 = sOut + s*OSAMP + j1*3;   // dummy row 25 -> padding slot
        or0[0] = o00; or0[1] = o01; or0[2] = o02;
        or1[0] = o10; or1[1] = o11; or1[2] = o12;
    }
    __syncthreads();

    float* og = out + (size_t)s0 * (JN*CIN);
    for (int i = t; i < nF; i += NT) {
        og[i] = sOut[(i/75)*OSAMP + i%75];
    }
}

extern "C" void kernel_launch(void* const* d_in, const int* in_sizes, int n_in,
                              void* d_out, int out_size)
{
    const float* x  = (const float*)d_in[0];
    const float* A1 = (const float*)d_in[1];
    const float* W1 = (const float*)d_in[2];
    const float* b1 = (const float*)d_in[3];
    const float* A2 = (const float*)d_in[4];
    const float* W2 = (const float*)d_in[5];
    const float* b2 = (const float*)d_in[6];
    const float* A3 = (const float*)d_in[7];
    const float* W3 = (const float*)d_in[8];
    const float* b3 = (const float*)d_in[9];
    const float* A4 = (const float*)d_in[10];
    const float* W4 = (const float*)d_in[11];
    const float* b4 = (const float*)d_in[12];
    float* out = (float*)d_out;

    const int S_total = in_sizes[0] / (JN * CIN);

    cudaFuncSetAttribute(gcn_kernel, cudaFuncAttributeMaxDynamicSharedMemorySize, SMEM_BYTES);

    prep_kernel<<<1, 256>>>(A1, A2, A3, A4, W1, b1, b2, W3, b3, W4);

    const int grid = (S_total + SPT - 1) / SPT;
    gcn_kernel<<<grid, NT, SMEM_BYTES>>>(x, W2, b4, out, S_total);
}

// round 3
// speedup vs baseline: 2.1719x; 1.0014x over previous
#include <cuda_runtime.h>
#include <math.h>

#define JN 25
#define CIN 3
#define HID 64
#define LAT 32

#define NT   256
#define TPS  13            // threads per sample (2 joints each, 26th is dummy)
#define SPT  19            // samples per block
#define ACT  (TPS*SPT)     // 247 active threads

#define XROW   4           // padded x row (floats)
#define XSAMP  104         // 26*4
#define PROW   36          // P row stride (floats), 16B-aligned
#define PSAMP  936         // 26*36
#define QSAMP  108         // 26*4 + pad
#define OSAMP  78          // 26*3 packed out staging

// shared layout (floats)
#define OFF_W1B  0         // 256   [64][4] = (W1[0][k],W1[1][k],W1[2][k],b1[k])
#define OFF_W2   256       // 2048  [64][32]
#define OFF_W3T  2304      // 2048  [64][32] transposed
#define OFF_W4B  4352      // 256   [64][4] = (W4[d][0..2], b23[d])
#define OFF_A1   4608      // 652 (rows 0..24 real, row 25 zero)
#define OFF_A23  5260      // 652
#define OFF_A4   5912      // 652
#define OFF_B4   6564      // 4
#define OFF_X    6568      // 19*104 = 1976   (reused as out staging, 19*78=1482)
#define OFF_P    8544      // 19*936 = 17784
#define OFF_Q    26328     // 19*108 = 2052
#define SMEM_FLOATS 28380
#define SMEM_BYTES  (SMEM_FLOATS * 4)

typedef unsigned long long u64;

__device__ float g_A1s[JN*JN];
__device__ float g_A2s[JN*JN];
__device__ float g_A3s[JN*JN];
__device__ float g_A23[JN*JN];
__device__ float g_A4s[JN*JN];
__device__ float g_b23[HID];
__device__ float g_W1b[HID*4];
__device__ float g_W3t[HID*LAT];
__device__ float g_W4b[HID*4];

// ---------- f32x2 helpers ----------
__device__ __forceinline__ u64 pk2(float v) {
    u64 r; asm("mov.b64 %0, {%1, %1};" : "=l"(r) : "f"(v)); return r;
}
__device__ __forceinline__ void upk(u64 v, float& lo, float& hi) {
    asm("mov.b64 {%0, %1}, %2;" : "=f"(lo), "=f"(hi) : "l"(v));
}
__device__ __forceinline__ u64 ffma2(u64 a, u64 b, u64 c) {
    u64 d; asm("fma.rn.f32x2 %0, %1, %2, %3;" : "=l"(d) : "l"(a), "l"(b), "l"(c)); return d;
}
__device__ __forceinline__ u64 addf2(u64 a, u64 b) {
    u64 d; asm("add.rn.f32x2 %0, %1, %2;" : "=l"(d) : "l"(a), "l"(b)); return d;
}

// ---------- prep ----------
__global__ void prep_kernel(const float* __restrict__ A1, const float* __restrict__ A2,
                            const float* __restrict__ A3, const float* __restrict__ A4,
                            const float* __restrict__ W1, const float* __restrict__ b1,
                            const float* __restrict__ b2, const float* __restrict__ W3,
                            const float* __restrict__ b3, const float* __restrict__ W4)
{
    int t = threadIdx.x;
    if (t < 4*JN) {
        int m = t / JN, r = t % JN;
        const float* src = (m==0) ? A1 : (m==1) ? A2 : (m==2) ? A3 : A4;
        float*       dst = (m==0) ? g_A1s : (m==1) ? g_A2s : (m==2) ? g_A3s : g_A4s;
        float mx = -1e30f;
        for (int k = 0; k < JN; k++) mx = fmaxf(mx, src[r*JN+k]);
        float e[JN]; float s = 0.f;
        for (int k = 0; k < JN; k++) { e[k] = expf(src[r*JN+k] - mx); s += e[k]; }
        float inv = 1.f / s;
        for (int k = 0; k < JN; k++) dst[r*JN+k] = e[k] * inv;
    }
    if (t >= 128 && t < 128 + HID) {
        int d = t - 128;
        float acc = b3[d];
        for (int c = 0; c < LAT; c++) acc = fmaf(b2[c], W3[c*HID+d], acc);
        g_b23[d] = acc;
    }
    __syncthreads();
    for (int i = t; i < JN*JN; i += blockDim.x) {
        int r = i / JN, c = i % JN;
        float acc = 0.f;
        for (int k = 0; k < JN; k++) acc = fmaf(g_A3s[r*JN+k], g_A2s[k*JN+c], acc);
        g_A23[i] = acc;
    }
    for (int i = t; i < HID*LAT; i += blockDim.x) {
        int d = i / LAT, c = i % LAT;
        g_W3t[i] = W3[c*HID + d];
    }
    for (int i = t; i < HID; i += blockDim.x) {
        g_W1b[4*i+0] = W1[0*HID+i];
        g_W1b[4*i+1] = W1[1*HID+i];
        g_W1b[4*i+2] = W1[2*HID+i];
        g_W1b[4*i+3] = b1[i];
        g_W4b[4*i+0] = W4[i*3+0];
        g_W4b[4*i+1] = W4[i*3+1];
        g_W4b[4*i+2] = W4[i*3+2];
        g_W4b[4*i+3] = g_b23[i];
    }
}

// ---------- main fused kernel ----------
__global__ void __launch_bounds__(NT, 2) gcn_kernel(
    const float* __restrict__ x,
    const float* __restrict__ W2,
    const float* __restrict__ b4,
    float* __restrict__ out, int S_total)
{
    extern __shared__ float sm[];
    float* sW1b = sm + OFF_W1B;
    float* sW2  = sm + OFF_W2;
    float* sW3t = sm + OFF_W3T;
    float* sW4b = sm + OFF_W4B;
    float* sA1  = sm + OFF_A1;
    float* sA23 = sm + OFF_A23;
    float* sA4  = sm + OFF_A4;
    float* sB4  = sm + OFF_B4;
    float* sX   = sm + OFF_X;
    float* sP   = sm + OFF_P;
    float* sQ   = sm + OFF_Q;
    float* sOut = sm + OFF_X;   // reuse

    const int t = threadIdx.x;

    // ---- stage constants (vectorized where possible) ----
    for (int i = t; i < HID; i += NT) {
        ((float4*)sW1b)[i] = ((const float4*)g_W1b)[i];
        ((float4*)sW4b)[i] = ((const float4*)g_W4b)[i];
    }
    for (int i = t; i < HID*LAT/4; i += NT) {
        ((float4*)sW2)[i]  = ((const float4*)W2)[i];
        ((float4*)sW3t)[i] = ((const float4*)g_W3t)[i];
    }
    for (int i = t; i < 652; i += NT) {
        sA1[i]  = (i < JN*JN) ? g_A1s[i] : 0.f;
        sA23[i] = (i < JN*JN) ? g_A23[i] : 0.f;
        sA4[i]  = (i < JN*JN) ? g_A4s[i] : 0.f;
    }
    if (t < 4) sB4[t] = (t < 3) ? b4[t] : 0.f;

    // ---- stage input (padded rows of 4) ----
    const int s0 = blockIdx.x * SPT;
    const int nS = min(SPT, S_total - s0);
    const int nF = nS * JN * CIN;
    const float* xg = x + (size_t)s0 * (JN*CIN);
    for (int i = t; i < nF; i += NT) {
        int si = i / 75, r = i % 75;
        sX[si*XSAMP + (r/3)*4 + (r%3)] = xg[i];
    }
    __syncthreads();

    const int s  = t / TPS;
    const int tj = t % TPS;
    const int j0 = 2*tj;
    const int j1 = 2*tj + 1;        // may be dummy row 25 (zero A rows)
    const bool active = (t < ACT) && (s < nS);

    u64 macc0[16], macc1[16];

    if (active) {
        // ---- stage 1: X' = A1s @ X (2 rows) ----
        float xa0 = 0.f, xa1 = 0.f, xa2 = 0.f;
        float xb0 = 0.f, xb1 = 0.f, xb2 = 0.f;
        {
            const float* a0r = sA1 + j0*JN;
            const float* a1r = sA1 + j1*JN;
            const float4* xs = (const float4*)(sX + s*XSAMP);
            #pragma unroll
            for (int k = 0; k < JN; k++) {
                float4 xr = xs[k];
                float a0 = a0r[k], a1 = a1r[k];
                xa0 = fmaf(a0, xr.x, xa0); xa1 = fmaf(a0, xr.y, xa1); xa2 = fmaf(a0, xr.z, xa2);
                xb0 = fmaf(a1, xr.x, xb0); xb1 = fmaf(a1, xr.y, xb1); xb2 = fmaf(a1, xr.z, xb2);
            }
        }
        // ---- stage 2+3 fused: P = relu(X'@W1+b1) @ W2 (on the fly, no H array) ----
        u64 pacc0[16], pacc1[16];
        #pragma unroll
        for (int p = 0; p < 16; p++) { pacc0[p] = 0ull; pacc1[p] = 0ull; }
        #pragma unroll 4
        for (int k = 0; k < HID; k++) {
            float4 wb = ((const float4*)sW1b)[k];
            float h0 = fmaf(xa2, wb.z, fmaf(xa1, wb.y, fmaf(xa0, wb.x, wb.w)));
            float h1 = fmaf(xb2, wb.z, fmaf(xb1, wb.y, fmaf(xb0, wb.x, wb.w)));
            h0 = fmaxf(h0, 0.f); h1 = fmaxf(h1, 0.f);
            u64 h0p = pk2(h0), h1p = pk2(h1);
            const ulonglong2* wr = (const ulonglong2*)(sW2 + k*LAT);
            #pragma unroll
            for (int q = 0; q < 8; q++) {
                ulonglong2 w = wr[q];
                pacc0[2*q]   = ffma2(h0p, w.x, pacc0[2*q]);
                pacc0[2*q+1] = ffma2(h0p, w.y, pacc0[2*q+1]);
                pacc1[2*q]   = ffma2(h1p, w.x, pacc1[2*q]);
                pacc1[2*q+1] = ffma2(h1p, w.y, pacc1[2*q+1]);
            }
        }
        // store P rows (dummy row 25 lands in padding, never read)
        {
            ulonglong2* pr0 = (ulonglong2*)(sP + s*PSAMP + j0*PROW);
            ulonglong2* pr1 = (ulonglong2*)(sP + s*PSAMP + j1*PROW);
            #pragma unroll
            for (int q = 0; q < 8; q++) {
                ulonglong2 v0, v1;
                v0.x = pacc0[2*q]; v0.y = pacc0[2*q+1];
                v1.x = pacc1[2*q]; v1.y = pacc1[2*q+1];
                pr0[q] = v0; pr1[q] = v1;
            }
        }
    }
    __syncthreads();

    if (active) {
        // ---- stage 4: M = A23 @ P (2 rows) ----
        #pragma unroll
        for (int p = 0; p < 16; p++) { macc0[p] = 0ull; macc1[p] = 0ull; }
        {
            const float* a0r = sA23 + j0*JN;
            const float* a1r = sA23 + j1*JN;
            const float* ps  = sP + s*PSAMP;
            #pragma unroll 5
            for (int k = 0; k < JN; k++) {
                u64 a0 = pk2(a0r[k]);
                u64 a1 = pk2(a1r[k]);
                const ulonglong2* pr = (const ulonglong2*)(ps + k*PROW);
                #pragma unroll
                for (int q = 0; q < 8; q++) {
                    ulonglong2 w = pr[q];
                    macc0[2*q]   = ffma2(a0, w.x, macc0[2*q]);
                    macc0[2*q+1] = ffma2(a0, w.y, macc0[2*q+1]);
                    macc1[2*q]   = ffma2(a1, w.x, macc1[2*q]);
                    macc1[2*q+1] = ffma2(a1, w.y, macc1[2*q+1]);
                }
            }
        }
        // ---- stage 5+6 fused: Q = relu(M@W3 + b23) @ W4 (dot-product form) ----
        float q00 = 0.f, q01 = 0.f, q02 = 0.f;
        float q10 = 0.f, q11 = 0.f, q12 = 0.f;
        #pragma unroll 2
        for (int d = 0; d < HID; d++) {
            const ulonglong2* wr = (const ulonglong2*)(sW3t + d*LAT);
            u64 aA0 = 0ull, aB0 = 0ull, aA1 = 0ull, aB1 = 0ull;
            #pragma unroll
            for (int q = 0; q < 8; q++) {
                ulonglong2 w = wr[q];
                aA0 = ffma2(macc0[2*q],   w.x, aA0);
                aB0 = ffma2(macc0[2*q+1], w.y, aB0);
                aA1 = ffma2(macc1[2*q],   w.x, aA1);
                aB1 = ffma2(macc1[2*q+1], w.y, aB1);
            }
            float4 w4 = ((const float4*)sW4b)[d];
            float l0, h0, l1, h1;
            upk(addf2(aA0, aB0), l0, h0);
            upk(addf2(aA1, aB1), l1, h1);
            float hd0 = fmaxf(l0 + h0 + w4.w, 0.f);
            float hd1 = fmaxf(l1 + h1 + w4.w, 0.f);
            q00 = fmaf(hd0, w4.x, q00); q01 = fmaf(hd0, w4.y, q01); q02 = fmaf(hd0, w4.z, q02);
            q10 = fmaf(hd1, w4.x, q10); q11 = fmaf(hd1, w4.y, q11); q12 = fmaf(hd1, w4.z, q12);
        }
        float* qr0 = sQ + s*QSAMP + j0*4;
        float* qr1 = sQ + s*QSAMP + j1*4;
        qr0[0] = q00; qr0[1] = q01; qr0[2] = q02;
        qr1[0] = q10; qr1[1] = q11; qr1[2] = q12;
    }
    __syncthreads();

    if (active) {
        // ---- stage 7: out = A4s @ Q + b4 (2 rows) ----
        float o00 = sB4[0], o01 = sB4[1], o02 = sB4[2];
        float o10 = o00, o11 = o01, o12 = o02;
        const float* a0r = sA4 + j0*JN;
        const float* a1r = sA4 + j1*JN;
        const float4* qs = (const float4*)(sQ + s*QSAMP);
        #pragma unroll
        for (int k = 0; k < JN; k++) {
            float4 qr = qs[k];
            float a0 = a0r[k], a1 = a1r[k];
            o00 = fmaf(a0, qr.x, o00); o01 = fmaf(a0, qr.y, o01); o02 = fmaf(a0, qr.z, o02);
            o10 = fmaf(a1, qr.x, o10); o11 = fmaf(a1, qr.y, o11); o12 = fmaf(a1, qr.z, o12);
        }
        float* or0 = sOut + s*OSAMP + j0*3;
        float* or1 = sOut + s*OSAMP + j1*3;   // dummy row 25 -> padding slot
        or0[0] = o00; or0[1] = o01; or0[2] = o02;
        or1[0] = o10; or1[1] = o11; or1[2] = o12;
    }
    __syncthreads();

    float* og = out + (size_t)s0 * (JN*CIN);
    for (int i = t; i < nF; i += NT) {
        og[i] = sOut[(i/75)*OSAMP + i%75];
    }
}

extern "C" void kernel_launch(void* const* d_in, const int* in_sizes, int n_in,
                              void* d_out, int out_size)
{
    const float* x  = (const float*)d_in[0];
    const float* A1 = (const float*)d_in[1];
    const float* W1 = (const float*)d_in[2];
    const float* b1 = (const float*)d_in[3];
    const float* A2 = (const float*)d_in[4];
    const float* W2 = (const float*)d_in[5];
    const float* b2 = (const float*)d_in[6];
    const float* A3 = (const float*)d_in[7];
    const float* W3 = (const float*)d_in[8];
    const float* b3 = (const float*)d_in[9];
    const float* A4 = (const float*)d_in[10];
    const float* W4 = (const float*)d_in[11];
    const float* b4 = (const float*)d_in[12];
    float* out = (float*)d_out;

    const int S_total = in_sizes[0] / (JN * CIN);

    cudaFuncSetAttribute(gcn_kernel, cudaFuncAttributeMaxDynamicSharedMemorySize, SMEM_BYTES);

    prep_kernel<<<1, 256>>>(A1, A2, A3, A4, W1, b1, b2, W3, b3, W4);

    const int grid = (S_total + SPT - 1) / SPT;
    gcn_kernel<<<grid, NT, SMEM_BYTES>>>(x, W2, b4, out, S_total);
}

// round 10
// speedup vs baseline: 3.1039x; 1.4291x over previous
#include <cuda_runtime.h>
#include <cuda_bf16.h>
#include <math.h>
#include <stdint.h>

#define JN 25
#define SPT 5
#define NTHR 128

typedef unsigned int u32;
typedef unsigned long long u64;

// dynamic smem byte offsets (all vector-access bases 16B-aligned)
#define OFF_WF   0        // 44 frags * 32 lanes * 16B = 22528
#define OFF_A1   22528    // 2500
#define OFF_A23  25028    // 2500
#define OFF_A4   27528    // 2500 (ends 30028)
#define OFF_B1   30032    // 256  (16B aligned)
#define OFF_B23  30288    // 256  (16B aligned)
#define OFF_B4   30544    // 16
#define OFF_XP   30560    // 128*16 = 2048
#define OFF_X    32608    // 125*16 = 2000 (+pad)
#define OFF_P    34624    // 128*144 = 18432
#define OFF_M    53056    // 128*144 = 18432
#define OFF_Q    71488    // 128*16 = 2048
#define SMEM_BYTES 73536

#define F2_BASE 0    // 8 frags  (K=16, N=64)
#define F3_BASE 8    // 16 frags (K=64, N=32)
#define F5_BASE 24   // 16 frags (K=32, N=64)
#define F6_BASE 40   // 4 frags  (K=64, N=8)
#define NFRAG 44

__device__ float g_A1s[JN*JN];
__device__ float g_A2s[JN*JN];
__device__ float g_A3s[JN*JN];
__device__ float g_A23[JN*JN];
__device__ float g_A4s[JN*JN];
__device__ float g_b23[64];
__device__ uint4 g_WF[NFRAG*32];

// ---------- helpers ----------
__device__ __forceinline__ u64 pk2(float v) { u64 r; asm("mov.b64 %0, {%1, %1};" : "=l"(r) : "f"(v)); return r; }
__device__ __forceinline__ void upk(u64 v, float& lo, float& hi) { asm("mov.b64 {%0, %1}, %2;" : "=f"(lo), "=f"(hi) : "l"(v)); }
__device__ __forceinline__ u64 ffma2(u64 a, u64 b, u64 c) { u64 d; asm("fma.rn.f32x2 %0, %1, %2, %3;" : "=l"(d) : "l"(a), "l"(b), "l"(c)); return d; }
__device__ __forceinline__ u32 pkbf(float a, float b) {
    __nv_bfloat162 v = __floats2bfloat162_rn(a, b);
    return *(u32*)&v;
}
__device__ __forceinline__ void sp(float v, float& h, float& l) {
    __nv_bfloat16 hb = __float2bfloat16(v);
    h = __bfloat162float(hb);
    l = v - h;
}
__device__ __forceinline__ void mma16816(float* d, u32 a0, u32 a1, u32 a2, u32 a3, u32 b0, u32 b1) {
    asm volatile("mma.sync.aligned.m16n8k16.row.col.f32.bf16.bf16.f32 "
        "{%0,%1,%2,%3}, {%4,%5,%6,%7}, {%8,%9}, {%0,%1,%2,%3};"
        : "+f"(d[0]), "+f"(d[1]), "+f"(d[2]), "+f"(d[3])
        : "r"(a0), "r"(a1), "r"(a2), "r"(a3), "r"(b0), "r"(b1));
}
// relu + bf16-split two D-frags (8 f32) into next-layer A-frags (hi, lo)
__device__ __forceinline__ void cvt_frag(const float* e03, const float* e47, u32* ah, u32* al) {
    float h[8], l[8];
    #pragma unroll
    for (int i = 0; i < 4; i++) { float v = fmaxf(e03[i], 0.f); sp(v, h[i], l[i]); }
    #pragma unroll
    for (int i = 0; i < 4; i++) { float v = fmaxf(e47[i], 0.f); sp(v, h[4+i], l[4+i]); }
    ah[0] = pkbf(h[0], h[1]); ah[1] = pkbf(h[2], h[3]); ah[2] = pkbf(h[4], h[5]); ah[3] = pkbf(h[6], h[7]);
    al[0] = pkbf(l[0], l[1]); al[1] = pkbf(l[2], l[3]); al[2] = pkbf(l[4], l[5]); al[3] = pkbf(l[6], l[7]);
}

// ---------- prep ----------
__global__ void prep_kernel(const float* __restrict__ A1, const float* __restrict__ A2,
                            const float* __restrict__ A3, const float* __restrict__ A4,
                            const float* __restrict__ W1, const float* __restrict__ W2,
                            const float* __restrict__ b2, const float* __restrict__ W3,
                            const float* __restrict__ b3, const float* __restrict__ W4)
{
    int t = threadIdx.x;
    if (t < 4*JN) {
        int m = t / JN, r = t % JN;
        const float* src = (m==0) ? A1 : (m==1) ? A2 : (m==2) ? A3 : A4;
        float*       dst = (m==0) ? g_A1s : (m==1) ? g_A2s : (m==2) ? g_A3s : g_A4s;
        float mx = -1e30f;
        for (int k = 0; k < JN; k++) mx = fmaxf(mx, src[r*JN+k]);
        float e[JN]; float s = 0.f;
        for (int k = 0; k < JN; k++) { e[k] = expf(src[r*JN+k] - mx); s += e[k]; }
        float inv = 1.f / s;
        for (int k = 0; k < JN; k++) dst[r*JN+k] = e[k] * inv;
    }
    if (t >= 128 && t < 192) {
        int d = t - 128;
        float acc = b3[d];
        for (int c = 0; c < 32; c++) acc = fmaf(b2[c], W3[c*64+d], acc);
        g_b23[d] = acc;
    }
    __syncthreads();
    for (int i = t; i < JN*JN; i += blockDim.x) {
        int r = i / JN, c = i % JN;
        float acc = 0.f;
        for (int k = 0; k < JN; k++) acc = fmaf(g_A3s[r*JN+k], g_A2s[k*JN+c], acc);
        g_A23[i] = acc;
    }
    // weight B-fragments: lane holds B[k][n] at k=16kt+2t4(+{0,1},+8), n=8nt+g
    for (int i = t; i < NFRAG*32; i += blockDim.x) {
        int lane = i & 31, f = i >> 5;
        int t4 = lane & 3, g = lane >> 2;
        int kt = 0, nt = 0, layer;
        if (f < 8)       { layer = 0; nt = f; }
        else if (f < 24) { layer = 1; int q = f - 8;  kt = q >> 2; nt = q & 3; }
        else if (f < 40) { layer = 2; int q = f - 24; kt = q >> 3; nt = q & 7; }
        else             { layer = 3; kt = f - 40; }
        int n = 8*nt + g;
        int kb = 16*kt + 2*t4;
        float v[4];
        #pragma unroll
        for (int u = 0; u < 4; u++) {
            int k = kb + (u & 1) + (u >> 1) * 8;
            float val;
            if (layer == 0)      val = (k < 3) ? W1[k*64 + n] : 0.f;
            else if (layer == 1) val = W2[k*32 + n];
            else if (layer == 2) val = W3[k*64 + n];
            else                 val = (n < 3) ? W4[k*3 + n] : 0.f;
            v[u] = val;
        }
        float h[4], l[4];
        #pragma unroll
        for (int u = 0; u < 4; u++) sp(v[u], h[u], l[u]);
        uint4 o;
        o.x = pkbf(h[0], h[1]); o.y = pkbf(h[2], h[3]);
        o.z = pkbf(l[0], l[1]); o.w = pkbf(l[2], l[3]);
        g_WF[i] = o;
    }
}

// ---------- main ----------
__global__ void __launch_bounds__(NTHR) gcn_mma_kernel(
    const float* __restrict__ x,
    const float* __restrict__ b1g, const float* __restrict__ b4g,
    float* __restrict__ out, int S_total, int ntiles)
{
    extern __shared__ char smem[];
    const int t = threadIdx.x;
    const int wid = t >> 5;
    const int lane = t & 31;
    const int t4 = lane & 3;
    const int g = lane >> 2;
    const int rw = 32 * wid;

    const uint4* sWF = (const uint4*)(smem + OFF_WF);
    float* sA1  = (float*)(smem + OFF_A1);
    float* sA23 = (float*)(smem + OFF_A23);
    float* sA4  = (float*)(smem + OFF_A4);
    float* sB1  = (float*)(smem + OFF_B1);
    float* sB23 = (float*)(smem + OFF_B23);
    float* sB4  = (float*)(smem + OFF_B4);
    float* sX   = (float*)(smem + OFF_X);
    float* sP   = (float*)(smem + OFF_P);
    float* sQ   = (float*)(smem + OFF_Q);
    u32*   XpU  = (u32*)(smem + OFF_XP);
    u32*   MU   = (u32*)(smem + OFF_M);

    // init constants
    for (int i = t; i < NFRAG*32; i += NTHR) ((uint4*)(smem + OFF_WF))[i] = g_WF[i];
    for (int i = t; i < JN*JN; i += NTHR) { sA1[i] = g_A1s[i]; sA23[i] = g_A23[i]; sA4[i] = g_A4s[i]; }
    for (int i = t; i < 64; i += NTHR) { sB1[i] = b1g[i]; sB23[i] = g_b23[i]; }
    if (t < 4) sB4[t] = (t < 3) ? b4g[t] : 0.f;
    for (int i = t; i < 512; i += NTHR) XpU[i] = 0u;
    for (int i = t; i < 128*36; i += NTHR) MU[i] = 0u;
    for (int i = t; i < 512; i += NTHR) sQ[i] = 0.f;
    __syncthreads();

    const int jj = t % 25;
    const int ss = t / 25;

    for (int tile = blockIdx.x; tile < ntiles; tile += gridDim.x) {
        const int s0 = tile * SPT;
        const int nS = min(SPT, S_total - s0);
        const int nR = nS * 25;
        const int nF = nS * 75;
        const bool vrow = (t < nR);

        // load X (padded rows of 4)
        const float* xg = x + (size_t)s0 * 75;
        for (int i = t; i < nF; i += NTHR) sX[(i/3)*4 + (i%3)] = xg[i];
        __syncthreads();

        // ---- stage1 (rows): X' = A1s @ X, split+pack to Xp ----
        if (vrow) {
            float x0 = 0.f, x1 = 0.f, x2 = 0.f;
            const float* arow = sA1 + jj*25;
            const float4* xs = (const float4*)sX + ss*25;
            #pragma unroll
            for (int k = 0; k < 25; k++) {
                float4 v = xs[k]; float a = arow[k];
                x0 = fmaf(a, v.x, x0); x1 = fmaf(a, v.y, x1); x2 = fmaf(a, v.z, x2);
            }
            float h0,l0,h1,l1,h2,l2;
            sp(x0,h0,l0); sp(x1,h1,l1); sp(x2,h2,l2);
            uint4 xp;
            xp.x = pkbf(h0, h1); xp.y = pkbf(h2, 0.f);
            xp.z = pkbf(l0, l1); xp.w = pkbf(l2, 0.f);
            ((uint4*)XpU)[t] = xp;
        }
        __syncthreads();

        // ---- stage2+3 (frags): D3 = relu(X'@W1+b1) @ W2 ----
        float d3[2][4][4];
        {
            float d2[2][8][4];
            #pragma unroll
            for (int mt = 0; mt < 2; mt++)
                #pragma unroll
                for (int nt = 0; nt < 8; nt++)
                    #pragma unroll
                    for (int q = 0; q < 4; q++) d2[mt][nt][q] = 0.f;

            u32 xh0[2], xh1[2], xl0[2], xl1[2];
            #pragma unroll
            for (int mt = 0; mt < 2; mt++) {
                int rA = rw + 16*mt + g;
                xh0[mt] = (t4 < 2) ? XpU[rA*4 + t4]       : 0u;
                xh1[mt] = (t4 < 2) ? XpU[(rA+8)*4 + t4]   : 0u;
                xl0[mt] = (t4 < 2) ? XpU[rA*4 + 2 + t4]     : 0u;
                xl1[mt] = (t4 < 2) ? XpU[(rA+8)*4 + 2 + t4] : 0u;
            }
            #pragma unroll
            for (int nt = 0; nt < 8; nt++) {
                uint4 B = sWF[(F2_BASE + nt)*32 + lane];
                float2 bb = *(const float2*)(sB1 + 8*nt + 2*t4);
                #pragma unroll
                for (int mt = 0; mt < 2; mt++) {
                    mma16816(d2[mt][nt], xh0[mt], xh1[mt], 0u, 0u, B.x, B.y);
                    mma16816(d2[mt][nt], xh0[mt], xh1[mt], 0u, 0u, B.z, B.w);
                    mma16816(d2[mt][nt], xl0[mt], xl1[mt], 0u, 0u, B.x, B.y);
                    d2[mt][nt][0] += bb.x; d2[mt][nt][1] += bb.y;
                    d2[mt][nt][2] += bb.x; d2[mt][nt][3] += bb.y;
                }
            }
            #pragma unroll
            for (int mt = 0; mt < 2; mt++)
                #pragma unroll
                for (int nt = 0; nt < 4; nt++)
                    #pragma unroll
                    for (int q = 0; q < 4; q++) d3[mt][nt][q] = 0.f;
            #pragma unroll
            for (int kt = 0; kt < 4; kt++) {
                u32 ah[2][4], al[2][4];
                #pragma unroll
                for (int mt = 0; mt < 2; mt++)
                    cvt_frag(d2[mt][2*kt], d2[mt][2*kt+1], ah[mt], al[mt]);
                #pragma unroll
                for (int nt = 0; nt < 4; nt++) {
                    uint4 B = sWF[(F3_BASE + kt*4 + nt)*32 + lane];
                    #pragma unroll
                    for (int mt = 0; mt < 2; mt++) {
                        mma16816(d3[mt][nt], ah[mt][0], ah[mt][1], ah[mt][2], ah[mt][3], B.x, B.y);
                        mma16816(d3[mt][nt], ah[mt][0], ah[mt][1], ah[mt][2], ah[mt][3], B.z, B.w);
                        mma16816(d3[mt][nt], al[mt][0], al[mt][1], al[mt][2], al[mt][3], B.x, B.y);
                    }
                }
            }
        }
        // STS P (f32, row stride 36)
        #pragma unroll
        for (int mt = 0; mt < 2; mt++) {
            int rA = rw + 16*mt + g;
            #pragma unroll
            for (int nt = 0; nt < 4; nt++) {
                float2 v0; v0.x = d3[mt][nt][0]; v0.y = d3[mt][nt][1];
                float2 v1; v1.x = d3[mt][nt][2]; v1.y = d3[mt][nt][3];
                *(float2*)(sP + rA*36 + 8*nt + 2*t4) = v0;
                *(float2*)(sP + (rA+8)*36 + 8*nt + 2*t4) = v1;
            }
        }
        __syncthreads();

        // ---- stage4 (rows): M = A23 @ P, split+pack to M smem ----
        if (vrow) {
            u64 macc[16];
            #pragma unroll
            for (int p = 0; p < 16; p++) macc[p] = 0ull;
            const float* arow = sA23 + jj*25;
            const float* pbase = sP + ss*25*36;
            #pragma unroll 5
            for (int k = 0; k < 25; k++) {
                u64 a = pk2(arow[k]);
                const ulonglong2* pr = (const ulonglong2*)(pbase + k*36);
                #pragma unroll
                for (int q = 0; q < 8; q++) {
                    ulonglong2 w = pr[q];
                    macc[2*q]   = ffma2(a, w.x, macc[2*q]);
                    macc[2*q+1] = ffma2(a, w.y, macc[2*q+1]);
                }
            }
            u32* mrow = MU + t*36;
            #pragma unroll
            for (int p = 0; p < 16; p++) {
                float e0, e1; upk(macc[p], e0, e1);
                float h0, l0, h1, l1;
                sp(e0, h0, l0); sp(e1, h1, l1);
                mrow[p]      = pkbf(h0, h1);
                mrow[16 + p] = pkbf(l0, l1);
            }
        }
        __syncthreads();

        // ---- stage5 (frags): D5 = M @ W3 (+b23) ----
        float d5[2][8][4];
        #pragma unroll
        for (int mt = 0; mt < 2; mt++)
            #pragma unroll
            for (int nt = 0; nt < 8; nt++)
                #pragma unroll
                for (int q = 0; q < 4; q++) d5[mt][nt][q] = 0.f;
        #pragma unroll
        for (int kt = 0; kt < 2; kt++) {
            u32 ah[2][4], al[2][4];
            #pragma unroll
            for (int mt = 0; mt < 2; mt++) {
                int rA = rw + 16*mt + g;
                ah[mt][0] = MU[rA*36 + 8*kt + t4];
                ah[mt][1] = MU[(rA+8)*36 + 8*kt + t4];
                ah[mt][2] = MU[rA*36 + 8*kt + 4 + t4];
                ah[mt][3] = MU[(rA+8)*36 + 8*kt + 4 + t4];
                al[mt][0] = MU[rA*36 + 16 + 8*kt + t4];
                al[mt][1] = MU[(rA+8)*36 + 16 + 8*kt + t4];
                al[mt][2] = MU[rA*36 + 16 + 8*kt + 4 + t4];
                al[mt][3] = MU[(rA+8)*36 + 16 + 8*kt + 4 + t4];
            }
            #pragma unroll
            for (int nt = 0; nt < 8; nt++) {
                uint4 B = sWF[(F5_BASE + kt*8 + nt)*32 + lane];
                #pragma unroll
                for (int mt = 0; mt < 2; mt++) {
                    mma16816(d5[mt][nt], ah[mt][0], ah[mt][1], ah[mt][2], ah[mt][3], B.x, B.y);
                    mma16816(d5[mt][nt], ah[mt][0], ah[mt][1], ah[mt][2], ah[mt][3], B.z, B.w);
                    mma16816(d5[mt][nt], al[mt][0], al[mt][1], al[mt][2], al[mt][3], B.x, B.y);
                }
            }
        }
        #pragma unroll
        for (int nt = 0; nt < 8; nt++) {
            float2 bb = *(const float2*)(sB23 + 8*nt + 2*t4);
            #pragma unroll
            for (int mt = 0; mt < 2; mt++) {
                d5[mt][nt][0] += bb.x; d5[mt][nt][1] += bb.y;
                d5[mt][nt][2] += bb.x; d5[mt][nt][3] += bb.y;
            }
        }

        // ---- stage6 (frags): D6 = relu(D5) @ W4 ----
        float d6[2][4];
        #pragma unroll
        for (int mt = 0; mt < 2; mt++)
            #pragma unroll
            for (int q = 0; q < 4; q++) d6[mt][q] = 0.f;
        #pragma unroll
        for (int kt = 0; kt < 4; kt++) {
            uint4 B = sWF[(F6_BASE + kt)*32 + lane];
            #pragma unroll
            for (int mt = 0; mt < 2; mt++) {
                u32 ah[4], al[4];
                cvt_frag(d5[mt][2*kt], d5[mt][2*kt+1], ah, al);
                mma16816(d6[mt], ah[0], ah[1], ah[2], ah[3], B.x, B.y);
                mma16816(d6[mt], ah[0], ah[1], ah[2], ah[3], B.z, B.w);
                mma16816(d6[mt], al[0], al[1], al[2], al[3], B.x, B.y);
            }
        }
        // STS Q (cols 0..3; col3 is zero since W4 col3 = 0)
        if (t4 < 2) {
            #pragma unroll
            for (int mt = 0; mt < 2; mt++) {
                int rA = rw + 16*mt + g;
                float2 v0; v0.x = d6[mt][0]; v0.y = d6[mt][1];
                float2 v1; v1.x = d6[mt][2]; v1.y = d6[mt][3];
                *(float2*)(sQ + rA*4 + 2*t4) = v0;
                *(float2*)(sQ + (rA+8)*4 + 2*t4) = v1;
            }
        }
        __syncthreads();

        // ---- stage7 (rows): out = A4s @ Q + b4 ----
        if (vrow) {
            float o0 = sB4[0], o1 = sB4[1], o2 = sB4[2];
            const float* arow = sA4 + jj*25;
            const float4* qs = (const float4*)sQ + ss*25;
            #pragma unroll
            for (int k = 0; k < 25; k++) {
                float4 qv = qs[k]; float a = arow[k];
                o0 = fmaf(a, qv.x, o0); o1 = fmaf(a, qv.y, o1); o2 = fmaf(a, qv.z, o2);
            }
            float* og = out + (size_t)s0 * 75 + t*3;
            og[0] = o0; og[1] = o1; og[2] = o2;
        }
        __syncthreads();
    }
}

extern "C" void kernel_launch(void* const* d_in, const int* in_sizes, int n_in,
                              void* d_out, int out_size)
{
    const float* x  = (const float*)d_in[0];
    const float* A1 = (const float*)d_in[1];
    const float* W1 = (const float*)d_in[2];
    const float* b1 = (const float*)d_in[3];
    const float* A2 = (const float*)d_in[4];
    const float* W2 = (const float*)d_in[5];
    const float* b2 = (const float*)d_in[6];
    const float* A3 = (const float*)d_in[7];
    const float* W3 = (const float*)d_in[8];
    const float* b3 = (const float*)d_in[9];
    const float* A4 = (const float*)d_in[10];
    const float* W4 = (const float*)d_in[11];
    const float* b4 = (const float*)d_in[12];
    float* out = (float*)d_out;

    const int S_total = in_sizes[0] / 75;
    const int ntiles = (S_total + SPT - 1) / SPT;

    cudaFuncSetAttribute(gcn_mma_kernel, cudaFuncAttributeMaxDynamicSharedMemorySize, SMEM_BYTES);

    prep_kernel<<<1, 256>>>(A1, A2, A3, A4, W1, W2, b2, W3, b3, W4);

    int grid = ntiles < 296 ? ntiles : 296;
    gcn_mma_kernel<<<grid, NTHR, SMEM_BYTES>>>(x, b1, b4, out, S_total, ntiles);
}